// round 4
// baseline (speedup 1.0000x reference)
#include <cuda_runtime.h>
#include <cuda_bf16.h>
#include <cstdint>

#define EPS_BN 1e-5f

// ===================== helpers (arch-neutral PTX, sm_80-era) =====================
__device__ __forceinline__ uint32_t smem_to_u32(const void* p) {
    uint32_t a;
    asm("{ .reg .u64 t; cvta.to.shared.u64 t, %1; cvt.u32.u64 %0, t; }" : "=r"(a) : "l"(p));
    return a;
}
__device__ __forceinline__ void cp16(uint32_t dst, const void* src) {
    asm volatile("cp.async.cg.shared.global [%0], [%1], 16;\n" :: "r"(dst), "l"(src));
}
#define CP_COMMIT() asm volatile("cp.async.commit_group;\n" ::: "memory")
#define CP_WAIT(N)  asm volatile("cp.async.wait_group %0;\n" :: "n"(N) : "memory")

#define LDSM_X4(r, addr) \
    asm volatile("ldmatrix.sync.aligned.m8n8.x4.shared.b16 {%0,%1,%2,%3}, [%4];" \
        : "=r"((r)[0]), "=r"((r)[1]), "=r"((r)[2]), "=r"((r)[3]) : "r"(addr))

#define MMA_S8(c, a0, a1, a2, a3, b0, b1) \
    asm volatile("mma.sync.aligned.m16n8k32.row.col.s32.s8.s8.s32 " \
        "{%0,%1,%2,%3}, {%4,%5,%6,%7}, {%8,%9}, {%0,%1,%2,%3};" \
        : "+r"((c)[0]), "+r"((c)[1]), "+r"((c)[2]), "+r"((c)[3]) \
        : "r"(a0), "r"(a1), "r"(a2), "r"(a3), "r"(b0), "r"(b1))

// ===================== static device workspace =====================
__device__ __align__(256) int8_t g_A0[32768u * 832u];
__device__ __align__(256) int8_t g_A1[32768u * 1024u];
__device__ __align__(256) int8_t g_A2[32768u * 1024u];
__device__ __align__(256) int8_t g_W1[1024u * 832u];
__device__ __align__(256) int8_t g_W2[1024u * 1024u];
__device__ __align__(256) int8_t g_W3[1024u * 1024u];
__device__ __align__(256) int8_t g_W4[16u * 1024u];     // padded to 16 rows (zeros)

// ===================== sign-pack: block per row, no division =====================
__global__ void sign_pack_row(const float* __restrict__ src, int8_t* __restrict__ dst,
                              int srcRows, int K, int KP) {
    int r = blockIdx.x;
    const float* s = src + (size_t)r * K;
    int8_t* d = dst + (size_t)r * KP;
    for (int c = threadIdx.x; c < KP; c += blockDim.x) {
        int8_t v = 0;
        if (r < srcRows && c < K) v = (s[c] >= 0.0f) ? (int8_t)1 : (int8_t)-1;
        d[c] = v;
    }
}

// ===================== pipelined s8 GEMM + BN + sign =====================
// CTA 128x128x64, 4 warps (warp tile 64x64), 4-stage cp.async pipeline,
// register-direct epilogue (no smem C spill).
#define LDS_ROW  80               // byte stride of staged s8 rows (conflict-free LDSM)
#define ST_BYTES (256 * LDS_ROW)  // 20480: A rows [0,128) + B rows [0,128)
#define NSTAGE   4
#define SM_TOTAL (NSTAGE * ST_BYTES)  // 81920

__global__ void __launch_bounds__(128, 2)
bgemm_mma(const int8_t* __restrict__ A, const int8_t* __restrict__ W, int KP,
          const float* __restrict__ bias, const float* __restrict__ gamma,
          const float* __restrict__ beta, const float* __restrict__ mean,
          const float* __restrict__ var, int8_t* __restrict__ Aout) {
    extern __shared__ char smc[];
    __shared__ float s_scale[128];
    __shared__ float s_shift[128];

    const int t      = threadIdx.x;
    const int lane   = t & 31;
    const int wid    = t >> 5;
    const int warp_m = wid & 1;          // 2 warp-rows of 64
    const int warp_n = wid >> 1;         // 2 warp-cols of 64
    const int row0   = blockIdx.y * 128;
    const int col0   = blockIdx.x * 128;
    const uint32_t smem_base = smem_to_u32(smc);

    {
        int j = col0 + t;                // blockDim == 128
        float sv = gamma[j] * rsqrtf(var[j] + EPS_BN);
        s_scale[t] = sv;
        s_shift[t] = sv * (bias[j] - mean[j]) + beta[j];
    }

    const int8_t* gAb = A + (size_t)row0 * KP;
    const int8_t* gBb = W + (size_t)col0 * KP;

    int acc[4][8][4];
#pragma unroll
    for (int i = 0; i < 4; ++i)
#pragma unroll
        for (int j = 0; j < 8; ++j)
#pragma unroll
            for (int k = 0; k < 4; ++k) acc[i][j][k] = 0;

    const int NK = KP >> 6;

#define ISSUE(kt) do {                                                        \
        int _st = (kt) & (NSTAGE - 1);                                        \
        uint32_t _sA = smem_base + _st * ST_BYTES;                            \
        uint32_t _sB = _sA + 128 * LDS_ROW;                                   \
        const int8_t* _gA = gAb + (kt) * 64;                                  \
        const int8_t* _gB = gBb + (kt) * 64;                                  \
        _Pragma("unroll")                                                     \
        for (int _l = 0; _l < 4; ++_l) {                                      \
            int _q = t + _l * 128;       /* 0..511 */                         \
            int _r = _q >> 2, _o = (_q & 3) << 4;                             \
            cp16(_sA + _r * LDS_ROW + _o, _gA + (size_t)_r * KP + _o);        \
            cp16(_sB + _r * LDS_ROW + _o, _gB + (size_t)_r * KP + _o);        \
        }                                                                     \
    } while (0)

    ISSUE(0); CP_COMMIT();
    ISSUE(1); CP_COMMIT();
    ISSUE(2); CP_COMMIT();

    const int a_rsel = (lane & 15);
    const int k_off  = (lane >> 4) << 4;

    for (int kt = 0; kt < NK; ++kt) {
        CP_WAIT(2);
        __syncthreads();
        if (kt + 3 < NK) ISSUE(kt + 3);
        CP_COMMIT();

        const uint32_t stb  = smem_base + (kt & (NSTAGE - 1)) * ST_BYTES;
        const uint32_t aBase = stb + (warp_m * 64 + a_rsel) * LDS_ROW + k_off;
        const uint32_t bBase = stb + 128 * LDS_ROW + (warp_n * 64 + a_rsel) * LDS_ROW + k_off;

#pragma unroll
        for (int s = 0; s < 2; ++s) {            // two k=32 steps
            uint32_t af[4][4], bf[4][4];
#pragma unroll
            for (int mf = 0; mf < 4; ++mf)
                LDSM_X4(af[mf], aBase + mf * 16 * LDS_ROW + s * 32);
#pragma unroll
            for (int p = 0; p < 4; ++p)
                LDSM_X4(bf[p], bBase + p * 16 * LDS_ROW + s * 32);
#pragma unroll
            for (int mf = 0; mf < 4; ++mf)
#pragma unroll
                for (int nf = 0; nf < 8; ++nf)
                    MMA_S8(acc[mf][nf],
                           af[mf][0], af[mf][1], af[mf][2], af[mf][3],
                           bf[nf >> 1][nf & 1], bf[nf >> 1][(nf & 1) + 2]);
        }
    }
    CP_WAIT(0);

    // register-direct epilogue: BN + sign -> char2 stores
    {
        const int rA = warp_m * 64 + (lane >> 2);
        const int cA = warp_n * 64 + (lane & 3) * 2;
#pragma unroll
        for (int mf = 0; mf < 4; ++mf) {
#pragma unroll
            for (int nf = 0; nf < 8; ++nf) {
                int lc = cA + nf * 8;
                float sc0 = s_scale[lc],     sh0 = s_shift[lc];
                float sc1 = s_scale[lc + 1], sh1 = s_shift[lc + 1];
                int r0 = row0 + rA + mf * 16;
                int gc = col0 + lc;
                char2 v0, v1;
                v0.x = (sc0 * (float)acc[mf][nf][0] + sh0 >= 0.0f) ? 1 : -1;
                v0.y = (sc1 * (float)acc[mf][nf][1] + sh1 >= 0.0f) ? 1 : -1;
                v1.x = (sc0 * (float)acc[mf][nf][2] + sh0 >= 0.0f) ? 1 : -1;
                v1.y = (sc1 * (float)acc[mf][nf][3] + sh1 >= 0.0f) ? 1 : -1;
                *(char2*)(Aout + (size_t)r0 * 1024 + gc)       = v0;
                *(char2*)(Aout + (size_t)(r0 + 8) * 1024 + gc) = v1;
            }
        }
    }
}

// ===================== layer 4 via mma: N=16 (10 real), K=1024 =====================
__global__ void __launch_bounds__(256)
final_mma(const int8_t* __restrict__ A, const int8_t* __restrict__ W,  // W: 16x1024, rows 10-15 zero
          const float* __restrict__ bias, const float* __restrict__ gamma,
          const float* __restrict__ beta, const float* __restrict__ mean,
          const float* __restrict__ var, float* __restrict__ out) {
    const int lane = threadIdx.x & 31;
    const int wid  = threadIdx.x >> 5;
    const int row0 = (blockIdx.x * 8 + wid) * 16;

    const int8_t* Ar = A + (size_t)row0 * 1024;
    int acc[2][4];
#pragma unroll
    for (int i = 0; i < 2; ++i)
#pragma unroll
        for (int k = 0; k < 4; ++k) acc[i][k] = 0;

    const int r4 = lane >> 2;          // 0..7
    const int c4 = (lane & 3) * 4;     // byte offset within 16B k-group

#pragma unroll 4
    for (int ks = 0; ks < 32; ++ks) {
        int kb = ks * 32;
        uint32_t a0 = *(const uint32_t*)(Ar + (size_t)r4 * 1024 + kb + c4);
        uint32_t a1 = *(const uint32_t*)(Ar + (size_t)(r4 + 8) * 1024 + kb + c4);
        uint32_t a2 = *(const uint32_t*)(Ar + (size_t)r4 * 1024 + kb + 16 + c4);
        uint32_t a3 = *(const uint32_t*)(Ar + (size_t)(r4 + 8) * 1024 + kb + 16 + c4);
#pragma unroll
        for (int nt = 0; nt < 2; ++nt) {
            uint32_t b0 = *(const uint32_t*)(W + (size_t)(nt * 8 + r4) * 1024 + kb + c4);
            uint32_t b1 = *(const uint32_t*)(W + (size_t)(nt * 8 + r4) * 1024 + kb + 16 + c4);
            MMA_S8(acc[nt], a0, a1, a2, a3, b0, b1);
        }
    }

#pragma unroll
    for (int nt = 0; nt < 2; ++nt)
#pragma unroll
        for (int k = 0; k < 4; ++k) {
            int c = nt * 8 + (lane & 3) * 2 + (k & 1);
            int r = row0 + (lane >> 2) + (k >> 1) * 8;
            if (c < 10) {
                float sv = gamma[c] * rsqrtf(var[c] + EPS_BN);
                out[(size_t)r * 10 + c] =
                    sv * ((float)acc[nt][k] + bias[c] - mean[c]) + beta[c];
            }
        }
}

// ===================== launch =====================
extern "C" void kernel_launch(void* const* d_in, const int* in_sizes, int n_in,
                              void* d_out, int out_size) {
    const float* x  = (const float*)d_in[0];
    const float* W1 = (const float*)d_in[1];
    const float* b1 = (const float*)d_in[2];
    const float* g1 = (const float*)d_in[3];
    const float* be1= (const float*)d_in[4];
    const float* m1 = (const float*)d_in[5];
    const float* v1 = (const float*)d_in[6];
    const float* W2 = (const float*)d_in[7];
    const float* b2 = (const float*)d_in[8];
    const float* g2 = (const float*)d_in[9];
    const float* be2= (const float*)d_in[10];
    const float* m2 = (const float*)d_in[11];
    const float* v2 = (const float*)d_in[12];
    const float* W3 = (const float*)d_in[13];
    const float* b3 = (const float*)d_in[14];
    const float* g3 = (const float*)d_in[15];
    const float* be3= (const float*)d_in[16];
    const float* m3 = (const float*)d_in[17];
    const float* v3 = (const float*)d_in[18];
    const float* W4 = (const float*)d_in[19];
    const float* b4 = (const float*)d_in[20];
    const float* g4 = (const float*)d_in[21];
    const float* be4= (const float*)d_in[22];
    const float* m4 = (const float*)d_in[23];
    const float* v4 = (const float*)d_in[24];

    int8_t *a0, *a1, *a2, *w1, *w2, *w3, *w4;
    cudaGetSymbolAddress((void**)&a0, g_A0);
    cudaGetSymbolAddress((void**)&a1, g_A1);
    cudaGetSymbolAddress((void**)&a2, g_A2);
    cudaGetSymbolAddress((void**)&w1, g_W1);
    cudaGetSymbolAddress((void**)&w2, g_W2);
    cudaGetSymbolAddress((void**)&w3, g_W3);
    cudaGetSymbolAddress((void**)&w4, g_W4);

    const int M = 32768;

    sign_pack_row<<<M, 256>>>(x, a0, M, 784, 832);
    sign_pack_row<<<1024, 256>>>(W1, w1, 1024, 784, 832);
    sign_pack_row<<<1024, 256>>>(W2, w2, 1024, 1024, 1024);
    sign_pack_row<<<1024, 256>>>(W3, w3, 1024, 1024, 1024);
    sign_pack_row<<<16, 256>>>(W4, w4, 10, 1024, 1024);   // rows 10-15 -> 0

    cudaFuncSetAttribute(bgemm_mma, cudaFuncAttributeMaxDynamicSharedMemorySize, SM_TOTAL);

    dim3 grid(8, M / 128);   // x = N tiles, y = M tiles

    bgemm_mma<<<grid, 128, SM_TOTAL>>>(a0, w1, 832,  b1, g1, be1, m1, v1, a1);
    bgemm_mma<<<grid, 128, SM_TOTAL>>>(a1, w2, 1024, b2, g2, be2, m2, v2, a2);
    bgemm_mma<<<grid, 128, SM_TOTAL>>>(a2, w3, 1024, b3, g3, be3, m3, v3, a1);

    final_mma<<<M / 128, 256>>>(a1, w4, b4, g4, be4, m4, v4, (float*)d_out);
}

// round 5
// speedup vs baseline: 1.0201x; 1.0201x over previous
#include <cuda_runtime.h>
#include <cuda_bf16.h>
#include <cstdint>

#define EPS_BN 1e-5f

// ===================== PTX helpers (sm_90 mainline; OK for sm_103 non-a) =====================
__device__ __forceinline__ uint32_t smem_to_u32(const void* p) {
    uint32_t a;
    asm("{ .reg .u64 t; cvta.to.shared.u64 t, %1; cvt.u32.u64 %0, t; }" : "=r"(a) : "l"(p));
    return a;
}
#define MBARRIER_INIT(addr, count) \
    asm volatile("mbarrier.init.shared.b64 [%0], %1;" :: "r"((uint32_t)(addr)), "r"((uint32_t)(count)) : "memory")
#define MBARRIER_EXPECT_TX(addr, tx) \
    asm volatile("mbarrier.arrive.expect_tx.shared.b64 _, [%0], %1;" :: "r"((uint32_t)(addr)), "r"((uint32_t)(tx)) : "memory")
#define MBARRIER_ARRIVE(addr) \
    asm volatile("mbarrier.arrive.shared.b64 _, [%0];" :: "r"((uint32_t)(addr)) : "memory")

#define MBARRIER_WAIT_PARITY(mbar_smem_addr, phase_parity) do { \
    uint32_t _mbar = (uint32_t)(mbar_smem_addr); \
    uint32_t _parity = (uint32_t)(phase_parity); \
    uint32_t _done; \
    asm volatile("{\n\t.reg .pred p;\n\t" \
        "mbarrier.try_wait.parity.acquire.cta.shared::cta.b64 p, [%1], %2;\n\t" \
        "selp.b32 %0, 1, 0, p;\n\t}" : "=r"(_done) : "r"(_mbar), "r"(_parity) : "memory"); \
    if (!_done) { \
        asm volatile("{\n\t.reg .pred P1;\n\t" \
            "WAIT_LOOP_%=:\n\t" \
            "mbarrier.try_wait.parity.acquire.cta.shared::cta.b64 P1, [%0], %1, 0x989680;\n\t" \
            "@P1 bra.uni WAIT_DONE_%=;\n\t" \
            "bra.uni WAIT_LOOP_%=;\n\t" \
            "WAIT_DONE_%=:\n\t}" :: "r"(_mbar), "r"(_parity) : "memory"); \
    } \
} while(0)

__device__ __forceinline__ void bulk_g2s(uint32_t dst, const void* src, uint32_t bytes, uint32_t mbar) {
    asm volatile("cp.async.bulk.shared::cta.global.mbarrier::complete_tx::bytes [%0], [%1], %2, [%3];"
        :: "r"(dst), "l"(src), "r"(bytes), "r"(mbar) : "memory");
}

#define LDSM_X4(r, addr) \
    asm volatile("ldmatrix.sync.aligned.m8n8.x4.shared.b16 {%0,%1,%2,%3}, [%4];" \
        : "=r"((r)[0]), "=r"((r)[1]), "=r"((r)[2]), "=r"((r)[3]) : "r"(addr))

#define MMA_S8(c, a0, a1, a2, a3, b0, b1) \
    asm volatile("mma.sync.aligned.m16n8k32.row.col.s32.s8.s8.s32 " \
        "{%0,%1,%2,%3}, {%4,%5,%6,%7}, {%8,%9}, {%0,%1,%2,%3};" \
        : "+r"((c)[0]), "+r"((c)[1]), "+r"((c)[2]), "+r"((c)[3]) \
        : "r"(a0), "r"(a1), "r"(a2), "r"(a3), "r"(b0), "r"(b1))

// Panel: 128 rows x 64 bytes = 8192 B, 16B-chunk swizzle within row.
__host__ __device__ __forceinline__ int swz_off(int r, int c) {     // r:0..127, c:0..63
    int chunk = (c >> 4) + (r >> 1);
    return r * 64 + ((chunk & 3) << 4) + (c & 15);
}

// ===================== static device workspace (panel layouts) =====================
__device__ __align__(256) int8_t g_A0[32768u * 896u];   // 256 mp x 14 kp panels
__device__ __align__(256) int8_t g_A1[32768u * 1024u];  // 256 x 16
__device__ __align__(256) int8_t g_A2[32768u * 1024u];
__device__ __align__(256) int8_t g_W1[1024u * 896u];    // 8 np x 14 kp
__device__ __align__(256) int8_t g_W2[1024u * 1024u];   // 8 x 16
__device__ __align__(256) int8_t g_W3[1024u * 1024u];
__device__ __align__(256) int8_t g_W4[16u * 1024u];     // plain row-major, rows 10..15 zero

// ===================== pack: float -> sign-int8 swizzled panels =====================
__global__ void pack_panels(const float* __restrict__ src, int8_t* __restrict__ dst,
                            int Kreal, int KPAN) {
    int mp = blockIdx.x, kp = blockIdx.y;
    int8_t* d = dst + ((size_t)mp * KPAN + kp) * 8192;
    const float* s = src + (size_t)mp * 128 * Kreal + kp * 64;
    for (int i = threadIdx.x; i < 8192; i += 256) {
        int r = i >> 6, c = i & 63;
        int8_t v = 0;
        if (kp * 64 + c < Kreal) v = (s[(size_t)r * Kreal + c] >= 0.0f) ? (int8_t)1 : (int8_t)-1;
        d[swz_off(r, c)] = v;
    }
}

__global__ void pack_w4(const float* __restrict__ src, int8_t* __restrict__ dst) {
    int i = blockIdx.x * 256 + threadIdx.x;        // 16384
    if (i >= 16384) return;
    int r = i >> 10, c = i & 1023;
    int8_t v = 0;
    if (r < 10) v = (src[r * 1024 + c] >= 0.0f) ? (int8_t)1 : (int8_t)-1;
    dst[i] = v;
}

// ===================== bulk-copy pipelined s8 GEMM + BN + sign =====================
// CTA 128x128; per k-tile (64): A panel + B panel via 2 cp.async.bulk.
// 4 stages x 16KB. 8 warps, warp tile 64x32 (R3 fragment mapping).
#define NSTAGE   4
#define STG_SZ   16384
#define SM_TOTAL (NSTAGE * STG_SZ)    // 65536

__global__ void __launch_bounds__(256, 2)
bgemm_bulk(const int8_t* __restrict__ A, const int8_t* __restrict__ W, int KPAN,
           const float* __restrict__ bias, const float* __restrict__ gamma,
           const float* __restrict__ beta, const float* __restrict__ mean,
           const float* __restrict__ var, int8_t* __restrict__ Aout) {
    extern __shared__ char smc[];
    __shared__ __align__(8) uint64_t mbars[2 * NSTAGE];   // full[0..3], empty[4..7]
    __shared__ float s_scale[128];
    __shared__ float s_shift[128];

    const int t      = threadIdx.x;
    const int lane   = t & 31;
    const int wid    = t >> 5;
    const int warp_m = wid & 1;           // 2 warp-rows of 64
    const int warp_n = wid >> 1;          // 4 warp-cols of 32
    const int row0   = blockIdx.y * 128;
    const int col0   = blockIdx.x * 128;
    const uint32_t smem_base = smem_to_u32(smc);
    const uint32_t mb_full   = smem_to_u32(&mbars[0]);
    const uint32_t mb_empty  = smem_to_u32(&mbars[NSTAGE]);

    if (t == 0) {
#pragma unroll
        for (int s = 0; s < NSTAGE; ++s) {
            MBARRIER_INIT(mb_full + s * 8, 1);
            MBARRIER_INIT(mb_empty + s * 8, 256);
        }
    }
    if (t < 128) {
        int j = col0 + t;
        float sv = gamma[j] * rsqrtf(var[j] + EPS_BN);
        s_scale[t] = sv;
        s_shift[t] = sv * (bias[j] - mean[j]) + beta[j];
    }
    __syncthreads();

    const int8_t* pA = A + (size_t)blockIdx.y * KPAN * 8192;
    const int8_t* pB = W + (size_t)blockIdx.x * KPAN * 8192;
    const int NK = KPAN;

#define PRODUCE(i) do {                                                        \
        int _s = (i) & 3;                                                      \
        MBARRIER_WAIT_PARITY(mb_empty + _s * 8, ((((i) >> 2) + 1) & 1));       \
        MBARRIER_EXPECT_TX(mb_full + _s * 8, STG_SZ);                          \
        uint32_t _d = smem_base + _s * STG_SZ;                                 \
        bulk_g2s(_d,        pA + (size_t)(i) * 8192, 8192, mb_full + _s * 8);  \
        bulk_g2s(_d + 8192, pB + (size_t)(i) * 8192, 8192, mb_full + _s * 8);  \
    } while (0)

    if (t == 0) {
        int np = NK < 3 ? NK : 3;
        for (int p = 0; p < np; ++p) PRODUCE(p);
    }

    int acc[4][4][4];
#pragma unroll
    for (int i = 0; i < 4; ++i)
#pragma unroll
        for (int j = 0; j < 4; ++j)
#pragma unroll
            for (int k = 0; k < 4; ++k) acc[i][j][k] = 0;

    // LDSM lane addressing within panel (swizzle invariant under +16 rows / mf,p)
    const int r0a   = warp_m * 64 + (lane & 15);
    const int r0b   = warp_n * 32 + (lane & 15);
    const int klane = lane >> 4;                 // 0/1 -> 16B chunk within k32 step
    const int rowtA = r0a * 64;
    const int rowtB = r0b * 64;
    const int csaA  = (klane + (r0a >> 1)) & 3;  // chunk swizzle bias
    const int csaB  = (klane + (r0b >> 1)) & 3;

    for (int kt = 0; kt < NK; ++kt) {
        if (t == 0 && kt + 3 < NK) PRODUCE(kt + 3);
        const int s4 = kt & 3;
        MBARRIER_WAIT_PARITY(mb_full + s4 * 8, (kt >> 2) & 1);

        const uint32_t stA = smem_base + s4 * STG_SZ;
        const uint32_t stB = stA + 8192;

#pragma unroll
        for (int s = 0; s < 2; ++s) {            // two k=32 steps
            uint32_t aAddr = stA + rowtA + ((((s << 1) + csaA) & 3) << 4);
            uint32_t bAddr = stB + rowtB + ((((s << 1) + csaB) & 3) << 4);
            uint32_t af[4][4], bf[2][4];
#pragma unroll
            for (int mf = 0; mf < 4; ++mf)
                LDSM_X4(af[mf], aAddr + mf * 1024);          // +16 rows = +1024 B
#pragma unroll
            for (int p = 0; p < 2; ++p)
                LDSM_X4(bf[p], bAddr + p * 1024);
#pragma unroll
            for (int mf = 0; mf < 4; ++mf)
#pragma unroll
                for (int nf = 0; nf < 4; ++nf)
                    MMA_S8(acc[mf][nf],
                           af[mf][0], af[mf][1], af[mf][2], af[mf][3],
                           bf[nf >> 1][nf & 1], bf[nf >> 1][(nf & 1) + 2]);
        }
        MBARRIER_ARRIVE(mb_empty + s4 * 8);
    }

    // epilogue: BN + sign -> char4 via one shuffle; write next layer's panels
    {
        const int rb = warp_m * 64 + (lane >> 2);
        const int lb = lane & 3;
#pragma unroll
        for (int mf = 0; mf < 4; ++mf) {
#pragma unroll
            for (int nf = 0; nf < 4; ++nf) {
                int lc = warp_n * 32 + lb * 2 + nf * 8;
                float sc0 = s_scale[lc],     sh0 = s_shift[lc];
                float sc1 = s_scale[lc + 1], sh1 = s_shift[lc + 1];
                uint32_t b0 = (sc0 * (float)acc[mf][nf][0] + sh0 >= 0.0f) ? 0x01u : 0xFFu;
                uint32_t b1 = (sc1 * (float)acc[mf][nf][1] + sh1 >= 0.0f) ? 0x01u : 0xFFu;
                uint32_t b2 = (sc0 * (float)acc[mf][nf][2] + sh0 >= 0.0f) ? 0x01u : 0xFFu;
                uint32_t b3 = (sc1 * (float)acc[mf][nf][3] + sh1 >= 0.0f) ? 0x01u : 0xFFu;
                uint32_t my01 = b0 | (b1 << 8);           // row rb+mf*16
                uint32_t my23 = b2 | (b3 << 8);           // row rb+mf*16+8
                uint32_t o01 = __shfl_xor_sync(0xffffffffu, my01, 1);
                uint32_t o23 = __shfl_xor_sync(0xffffffffu, my23, 1);
                uint32_t w; int r;
                if (lane & 1) { w = o23 | (my23 << 16); r = rb + mf * 16 + 8; }
                else          { w = my01 | (o01 << 16); r = rb + mf * 16; }
                int colg = warp_n * 32 + nf * 8 + ((lb >> 1) << 2);
                int gcol = col0 + colg;
                int8_t* pnl = Aout + (((size_t)blockIdx.y * 16) + (gcol >> 6)) * 8192;
                *(uint32_t*)(pnl + swz_off(r, gcol & 63)) = w;
            }
        }
    }
#undef PRODUCE
}

// ===================== layer 4 via mma: N=16 (10 real), A in panels =====================
__global__ void __launch_bounds__(256)
final_mma(const int8_t* __restrict__ A, const int8_t* __restrict__ W,
          const float* __restrict__ bias, const float* __restrict__ gamma,
          const float* __restrict__ beta, const float* __restrict__ mean,
          const float* __restrict__ var, float* __restrict__ out) {
    const int lane = threadIdx.x & 31;
    const int wid  = threadIdx.x >> 5;
    const int row0 = (blockIdx.x * 8 + wid) * 16;
    const int mp   = row0 >> 7;
    const int rl0  = row0 & 127;

    int acc[2][4];
#pragma unroll
    for (int i = 0; i < 2; ++i)
#pragma unroll
        for (int k = 0; k < 4; ++k) acc[i][k] = 0;

    const int r4 = lane >> 2;          // 0..7
    const int c4 = (lane & 3) * 4;     // byte within 16B chunk

#pragma unroll 4
    for (int ks = 0; ks < 32; ++ks) {
        int kb = ks * 32;
        const int8_t* pnl = A + ((size_t)mp * 16 + (kb >> 6)) * 8192;
        int cb = kb & 63;
        uint32_t a0 = *(const uint32_t*)(pnl + swz_off(rl0 + r4,     cb + c4));
        uint32_t a1 = *(const uint32_t*)(pnl + swz_off(rl0 + r4 + 8, cb + c4));
        uint32_t a2 = *(const uint32_t*)(pnl + swz_off(rl0 + r4,     cb + 16 + c4));
        uint32_t a3 = *(const uint32_t*)(pnl + swz_off(rl0 + r4 + 8, cb + 16 + c4));
#pragma unroll
        for (int nt = 0; nt < 2; ++nt) {
            uint32_t b0 = *(const uint32_t*)(W + (size_t)(nt * 8 + r4) * 1024 + kb + c4);
            uint32_t b1 = *(const uint32_t*)(W + (size_t)(nt * 8 + r4) * 1024 + kb + 16 + c4);
            MMA_S8(acc[nt], a0, a1, a2, a3, b0, b1);
        }
    }

#pragma unroll
    for (int nt = 0; nt < 2; ++nt)
#pragma unroll
        for (int k = 0; k < 4; ++k) {
            int c = nt * 8 + (lane & 3) * 2 + (k & 1);
            int r = row0 + (lane >> 2) + (k >> 1) * 8;
            if (c < 10) {
                float sv = gamma[c] * rsqrtf(var[c] + EPS_BN);
                out[(size_t)r * 10 + c] =
                    sv * ((float)acc[nt][k] + bias[c] - mean[c]) + beta[c];
            }
        }
}

// ===================== launch =====================
extern "C" void kernel_launch(void* const* d_in, const int* in_sizes, int n_in,
                              void* d_out, int out_size) {
    const float* x  = (const float*)d_in[0];
    const float* W1 = (const float*)d_in[1];
    const float* b1 = (const float*)d_in[2];
    const float* g1 = (const float*)d_in[3];
    const float* be1= (const float*)d_in[4];
    const float* m1 = (const float*)d_in[5];
    const float* v1 = (const float*)d_in[6];
    const float* W2 = (const float*)d_in[7];
    const float* b2 = (const float*)d_in[8];
    const float* g2 = (const float*)d_in[9];
    const float* be2= (const float*)d_in[10];
    const float* m2 = (const float*)d_in[11];
    const float* v2 = (const float*)d_in[12];
    const float* W3 = (const float*)d_in[13];
    const float* b3 = (const float*)d_in[14];
    const float* g3 = (const float*)d_in[15];
    const float* be3= (const float*)d_in[16];
    const float* m3 = (const float*)d_in[17];
    const float* v3 = (const float*)d_in[18];
    const float* W4 = (const float*)d_in[19];
    const float* b4 = (const float*)d_in[20];
    const float* g4 = (const float*)d_in[21];
    const float* be4= (const float*)d_in[22];
    const float* m4 = (const float*)d_in[23];
    const float* v4 = (const float*)d_in[24];

    int8_t *a0, *a1, *a2, *w1, *w2, *w3, *w4;
    cudaGetSymbolAddress((void**)&a0, g_A0);
    cudaGetSymbolAddress((void**)&a1, g_A1);
    cudaGetSymbolAddress((void**)&a2, g_A2);
    cudaGetSymbolAddress((void**)&w1, g_W1);
    cudaGetSymbolAddress((void**)&w2, g_W2);
    cudaGetSymbolAddress((void**)&w3, g_W3);
    cudaGetSymbolAddress((void**)&w4, g_W4);

    const int M = 32768;

    pack_panels<<<dim3(256, 14), 256>>>(x,  a0, 784,  14);
    pack_panels<<<dim3(8,   14), 256>>>(W1, w1, 784,  14);
    pack_panels<<<dim3(8,   16), 256>>>(W2, w2, 1024, 16);
    pack_panels<<<dim3(8,   16), 256>>>(W3, w3, 1024, 16);
    pack_w4<<<64, 256>>>(W4, w4);

    cudaFuncSetAttribute(bgemm_bulk, cudaFuncAttributeMaxDynamicSharedMemorySize, SM_TOTAL);

    dim3 grid(8, M / 128);   // x = N tiles (128), y = M tiles (128)

    bgemm_bulk<<<grid, 256, SM_TOTAL>>>(a0, w1, 14, b1, g1, be1, m1, v1, a1);
    bgemm_bulk<<<grid, 256, SM_TOTAL>>>(a1, w2, 16, b2, g2, be2, m2, v2, a2);
    bgemm_bulk<<<grid, 256, SM_TOTAL>>>(a2, w3, 16, b3, g3, be3, m3, v3, a1);

    final_mma<<<M / 128, 256>>>(a1, w4, b4, g4, be4, m4, v4, (float*)d_out);
}

// round 6
// speedup vs baseline: 1.1013x; 1.0796x over previous
#include <cuda_runtime.h>
#include <cuda_bf16.h>
#include <cstdint>

#define EPS_BN 1e-5f

// ===================== PTX helpers (sm_90 mainline; OK for sm_103 non-a) =====================
__device__ __forceinline__ uint32_t smem_to_u32(const void* p) {
    uint32_t a;
    asm("{ .reg .u64 t; cvta.to.shared.u64 t, %1; cvt.u32.u64 %0, t; }" : "=r"(a) : "l"(p));
    return a;
}
#define MBARRIER_INIT(addr, count) \
    asm volatile("mbarrier.init.shared.b64 [%0], %1;" :: "r"((uint32_t)(addr)), "r"((uint32_t)(count)) : "memory")
#define MBARRIER_EXPECT_TX(addr, tx) \
    asm volatile("mbarrier.arrive.expect_tx.shared.b64 _, [%0], %1;" :: "r"((uint32_t)(addr)), "r"((uint32_t)(tx)) : "memory")
#define MBARRIER_ARRIVE(addr) \
    asm volatile("mbarrier.arrive.shared.b64 _, [%0];" :: "r"((uint32_t)(addr)) : "memory")

#define MBARRIER_WAIT_PARITY(mbar_smem_addr, phase_parity) do { \
    uint32_t _mbar = (uint32_t)(mbar_smem_addr); \
    uint32_t _parity = (uint32_t)(phase_parity); \
    uint32_t _done; \
    asm volatile("{\n\t.reg .pred p;\n\t" \
        "mbarrier.try_wait.parity.acquire.cta.shared::cta.b64 p, [%1], %2;\n\t" \
        "selp.b32 %0, 1, 0, p;\n\t}" : "=r"(_done) : "r"(_mbar), "r"(_parity) : "memory"); \
    if (!_done) { \
        asm volatile("{\n\t.reg .pred P1;\n\t" \
            "WAIT_LOOP_%=:\n\t" \
            "mbarrier.try_wait.parity.acquire.cta.shared::cta.b64 P1, [%0], %1, 0x989680;\n\t" \
            "@P1 bra.uni WAIT_DONE_%=;\n\t" \
            "bra.uni WAIT_LOOP_%=;\n\t" \
            "WAIT_DONE_%=:\n\t}" :: "r"(_mbar), "r"(_parity) : "memory"); \
    } \
} while(0)

__device__ __forceinline__ void bulk_g2s(uint32_t dst, const void* src, uint32_t bytes, uint32_t mbar) {
    asm volatile("cp.async.bulk.shared::cta.global.mbarrier::complete_tx::bytes [%0], [%1], %2, [%3];"
        :: "r"(dst), "l"(src), "r"(bytes), "r"(mbar) : "memory");
}

#define LDSM_X4(r, addr) \
    asm volatile("ldmatrix.sync.aligned.m8n8.x4.shared.b16 {%0,%1,%2,%3}, [%4];" \
        : "=r"((r)[0]), "=r"((r)[1]), "=r"((r)[2]), "=r"((r)[3]) : "r"(addr))

#define MMA_S8(c, a0, a1, a2, a3, b0, b1) \
    asm volatile("mma.sync.aligned.m16n8k32.row.col.s32.s8.s8.s32 " \
        "{%0,%1,%2,%3}, {%4,%5,%6,%7}, {%8,%9}, {%0,%1,%2,%3};" \
        : "+r"((c)[0]), "+r"((c)[1]), "+r"((c)[2]), "+r"((c)[3]) \
        : "r"(a0), "r"(a1), "r"(a2), "r"(a3), "r"(b0), "r"(b1))

// Panel: 128 rows x 64 bytes = 8192 B, 16B-chunk swizzle within row.
__host__ __device__ __forceinline__ int swz_off(int r, int c) {     // r:0..127, c:0..63
    int chunk = (c >> 4) + (r >> 1);
    return r * 64 + ((chunk & 3) << 4) + (c & 15);
}

// ===================== static device workspace (panel layouts) =====================
__device__ __align__(256) int8_t g_A0[32768u * 896u];   // 256 mp x 14 kp panels
__device__ __align__(256) int8_t g_A1[32768u * 1024u];  // 256 x 16
__device__ __align__(256) int8_t g_A2[32768u * 1024u];
__device__ __align__(256) int8_t g_W1[1024u * 896u];    // 8 np x 14 kp
__device__ __align__(256) int8_t g_W2[1024u * 1024u];   // 8 x 16
__device__ __align__(256) int8_t g_W3[1024u * 1024u];
__device__ __align__(256) int8_t g_W4[16u * 1024u];     // plain row-major, rows 10..15 zero

// ===================== fused pack: ONE launch for all inputs =====================
__device__ __forceinline__ void pack_one(const float* __restrict__ src, int8_t* __restrict__ dst,
                                         int mp, int kp, int Kreal, int KPAN) {
    int8_t* d = dst + ((size_t)mp * KPAN + kp) * 8192;
    const float* s = src + (size_t)mp * 128 * Kreal + kp * 64;
    for (int i = threadIdx.x; i < 8192; i += 256) {
        int r = i >> 6, c = i & 63;
        int8_t v = 0;
        if (kp * 64 + c < Kreal) v = (s[(size_t)r * Kreal + c] >= 0.0f) ? (int8_t)1 : (int8_t)-1;
        d[swz_off(r, c)] = v;
    }
}

// grid = 3584 (x) + 112 (W1) + 128 (W2) + 128 (W3) + 16 (W4) = 3968 blocks
__global__ void pack_all(const float* __restrict__ x,  int8_t* __restrict__ a0,
                         const float* __restrict__ W1, int8_t* __restrict__ w1,
                         const float* __restrict__ W2, int8_t* __restrict__ w2,
                         const float* __restrict__ W3, int8_t* __restrict__ w3,
                         const float* __restrict__ W4, int8_t* __restrict__ w4) {
    int b = blockIdx.x;
    if (b < 3584)      { pack_one(x,  a0, b / 14,          b % 14,          784,  14); }
    else if (b < 3696) { b -= 3584; pack_one(W1, w1, b / 14, b % 14,        784,  14); }
    else if (b < 3824) { b -= 3696; pack_one(W2, w2, b >> 4, b & 15,        1024, 16); }
    else if (b < 3952) { b -= 3824; pack_one(W3, w3, b >> 4, b & 15,        1024, 16); }
    else {
        int r = b - 3952;                        // one row of W4 per block
        int c = threadIdx.x * 4;
        for (int u = 0; u < 4; ++u) {
            int8_t v = 0;
            if (r < 10) v = (W4[(size_t)r * 1024 + c + u] >= 0.0f) ? (int8_t)1 : (int8_t)-1;
            w4[(size_t)r * 1024 + c + u] = v;
        }
    }
}

// ===================== bulk-copy pipelined s8 GEMM + BN + sign =====================
// CTA 128x128; per k-tile (64): A panel + B panel via 2 cp.async.bulk.
// 4 stages x 16KB. 8 warps, warp tile 64x32.
#define NSTAGE   4
#define STG_SZ   16384
#define SM_TOTAL (NSTAGE * STG_SZ)    // 65536

__global__ void __launch_bounds__(256, 2)
bgemm_bulk(const int8_t* __restrict__ A, const int8_t* __restrict__ W, int KPAN,
           const float* __restrict__ bias, const float* __restrict__ gamma,
           const float* __restrict__ beta, const float* __restrict__ mean,
           const float* __restrict__ var, int8_t* __restrict__ Aout) {
    extern __shared__ char smc[];
    __shared__ __align__(8) uint64_t mbars[2 * NSTAGE];   // full[0..3], empty[4..7]
    __shared__ float s_scale[128];
    __shared__ float s_shift[128];

    const int t      = threadIdx.x;
    const int lane   = t & 31;
    const int wid    = t >> 5;
    const int warp_m = wid & 1;           // 2 warp-rows of 64
    const int warp_n = wid >> 1;          // 4 warp-cols of 32
    const int row0   = blockIdx.y * 128;
    const int col0   = blockIdx.x * 128;
    const uint32_t smem_base = smem_to_u32(smc);
    const uint32_t mb_full   = smem_to_u32(&mbars[0]);
    const uint32_t mb_empty  = smem_to_u32(&mbars[NSTAGE]);

    if (t == 0) {
#pragma unroll
        for (int s = 0; s < NSTAGE; ++s) {
            MBARRIER_INIT(mb_full + s * 8, 1);
            MBARRIER_INIT(mb_empty + s * 8, 8);   // one elected arrive per warp
        }
    }
    if (t < 128) {
        int j = col0 + t;
        float sv = gamma[j] * rsqrtf(var[j] + EPS_BN);
        s_scale[t] = sv;
        s_shift[t] = sv * (bias[j] - mean[j]) + beta[j];
    }
    __syncthreads();

    const int8_t* pA = A + (size_t)blockIdx.y * KPAN * 8192;
    const int8_t* pB = W + (size_t)blockIdx.x * KPAN * 8192;
    const int NK = KPAN;

#define PRODUCE(i) do {                                                        \
        int _s = (i) & 3;                                                      \
        MBARRIER_WAIT_PARITY(mb_empty + _s * 8, ((((i) >> 2) + 1) & 1));       \
        MBARRIER_EXPECT_TX(mb_full + _s * 8, STG_SZ);                          \
        uint32_t _d = smem_base + _s * STG_SZ;                                 \
        bulk_g2s(_d,        pA + (size_t)(i) * 8192, 8192, mb_full + _s * 8);  \
        bulk_g2s(_d + 8192, pB + (size_t)(i) * 8192, 8192, mb_full + _s * 8);  \
    } while (0)

    if (t == 0) {
        int np = NK < 3 ? NK : 3;
        for (int p = 0; p < np; ++p) PRODUCE(p);
    }

    int acc[4][4][4];
#pragma unroll
    for (int i = 0; i < 4; ++i)
#pragma unroll
        for (int j = 0; j < 4; ++j)
#pragma unroll
            for (int k = 0; k < 4; ++k) acc[i][j][k] = 0;

    // LDSM lane addressing within panel (swizzle invariant under +16 rows)
    const int r0a   = warp_m * 64 + (lane & 15);
    const int r0b   = warp_n * 32 + (lane & 15);
    const int klane = lane >> 4;                 // 0/1 -> 16B chunk within k32 step
    const int rowtA = r0a * 64;
    const int rowtB = r0b * 64;
    const int csaA  = (klane + (r0a >> 1)) & 3;  // chunk swizzle bias
    const int csaB  = (klane + (r0b >> 1)) & 3;

    for (int kt = 0; kt < NK; ++kt) {
        if (t == 0 && kt + 3 < NK) PRODUCE(kt + 3);
        const int s4 = kt & 3;
        MBARRIER_WAIT_PARITY(mb_full + s4 * 8, (kt >> 2) & 1);

        const uint32_t stA = smem_base + s4 * STG_SZ;
        const uint32_t stB = stA + 8192;

#pragma unroll
        for (int s = 0; s < 2; ++s) {            // two k=32 steps
            uint32_t aAddr = stA + rowtA + ((((s << 1) + csaA) & 3) << 4);
            uint32_t bAddr = stB + rowtB + ((((s << 1) + csaB) & 3) << 4);
            uint32_t af[4][4], bf[2][4];
#pragma unroll
            for (int mf = 0; mf < 4; ++mf)
                LDSM_X4(af[mf], aAddr + mf * 1024);          // +16 rows = +1024 B
#pragma unroll
            for (int p = 0; p < 2; ++p)
                LDSM_X4(bf[p], bAddr + p * 1024);
#pragma unroll
            for (int mf = 0; mf < 4; ++mf)
#pragma unroll
                for (int nf = 0; nf < 4; ++nf)
                    MMA_S8(acc[mf][nf],
                           af[mf][0], af[mf][1], af[mf][2], af[mf][3],
                           bf[nf >> 1][nf & 1], bf[nf >> 1][(nf & 1) + 2]);
        }
        if (lane == 0) MBARRIER_ARRIVE(mb_empty + s4 * 8);   // elected per-warp arrive
    }

    // ---- epilogue: BN + sign -> int8, gathered to STG.128 ----
    // After xor-1 shuffle: thread holds char4 for row R, cols base..base+3.
    // After xor-2 shuffle: thread holds int4 (16 cols) for row R.
    {
        const int rbase = warp_m * 64 + (lane >> 2) + ((lane & 1) ? 8 : 0);
        const int cbase = warp_n * 32 + ((lane & 2) ? 16 : 0);
        const int gcol  = col0 + cbase;
        int8_t* pnl = Aout + ((size_t)blockIdx.y * 16 + (gcol >> 6)) * 8192;
        const int cloc = gcol & 63;

#pragma unroll
        for (int mf = 0; mf < 4; ++mf) {
            uint32_t w[4];
#pragma unroll
            for (int nf = 0; nf < 4; ++nf) {
                int lc = warp_n * 32 + nf * 8 + (lane & 3) * 2;
                float sc0 = s_scale[lc],     sh0 = s_shift[lc];
                float sc1 = s_scale[lc + 1], sh1 = s_shift[lc + 1];
                uint32_t b0 = (sc0 * (float)acc[mf][nf][0] + sh0 >= 0.0f) ? 0x01u : 0xFFu;
                uint32_t b1 = (sc1 * (float)acc[mf][nf][1] + sh1 >= 0.0f) ? 0x01u : 0xFFu;
                uint32_t b2 = (sc0 * (float)acc[mf][nf][2] + sh0 >= 0.0f) ? 0x01u : 0xFFu;
                uint32_t b3 = (sc1 * (float)acc[mf][nf][3] + sh1 >= 0.0f) ? 0x01u : 0xFFu;
                uint32_t my01 = b0 | (b1 << 8);            // row rb+mf*16
                uint32_t my23 = b2 | (b3 << 8);            // row rb+mf*16+8
                uint32_t o01 = __shfl_xor_sync(0xffffffffu, my01, 1);
                uint32_t o23 = __shfl_xor_sync(0xffffffffu, my23, 1);
                w[nf] = (lane & 1) ? (o23 | (my23 << 16)) : (my01 | (o01 << 16));
            }
            uint32_t p0 = __shfl_xor_sync(0xffffffffu, w[0], 2);
            uint32_t p1 = __shfl_xor_sync(0xffffffffu, w[1], 2);
            uint32_t p2 = __shfl_xor_sync(0xffffffffu, w[2], 2);
            uint32_t p3 = __shfl_xor_sync(0xffffffffu, w[3], 2);
            int4 v = (lane & 2) ? make_int4((int)p2, (int)w[2], (int)p3, (int)w[3])
                                : make_int4((int)w[0], (int)p0, (int)w[1], (int)p1);
            int r = rbase + mf * 16;
            *(int4*)(pnl + swz_off(r, cloc)) = v;
        }
    }
#undef PRODUCE
}

// ===================== layer 4 via mma: N=16 (10 real), A in panels =====================
__global__ void __launch_bounds__(256)
final_mma(const int8_t* __restrict__ A, const int8_t* __restrict__ W,
          const float* __restrict__ bias, const float* __restrict__ gamma,
          const float* __restrict__ beta, const float* __restrict__ mean,
          const float* __restrict__ var, float* __restrict__ out) {
    const int lane = threadIdx.x & 31;
    const int wid  = threadIdx.x >> 5;
    const int row0 = (blockIdx.x * 8 + wid) * 16;
    const int mp   = row0 >> 7;
    const int rl0  = row0 & 127;

    int acc[2][4];
#pragma unroll
    for (int i = 0; i < 2; ++i)
#pragma unroll
        for (int k = 0; k < 4; ++k) acc[i][k] = 0;

    const int r4 = lane >> 2;          // 0..7
    const int c4 = (lane & 3) * 4;     // byte within 16B chunk

#pragma unroll 4
    for (int ks = 0; ks < 32; ++ks) {
        int kb = ks * 32;
        const int8_t* pnl = A + ((size_t)mp * 16 + (kb >> 6)) * 8192;
        int cb = kb & 63;
        uint32_t a0 = *(const uint32_t*)(pnl + swz_off(rl0 + r4,     cb + c4));
        uint32_t a1 = *(const uint32_t*)(pnl + swz_off(rl0 + r4 + 8, cb + c4));
        uint32_t a2 = *(const uint32_t*)(pnl + swz_off(rl0 + r4,     cb + 16 + c4));
        uint32_t a3 = *(const uint32_t*)(pnl + swz_off(rl0 + r4 + 8, cb + 16 + c4));
#pragma unroll
        for (int nt = 0; nt < 2; ++nt) {
            uint32_t b0 = *(const uint32_t*)(W + (size_t)(nt * 8 + r4) * 1024 + kb + c4);
            uint32_t b1 = *(const uint32_t*)(W + (size_t)(nt * 8 + r4) * 1024 + kb + 16 + c4);
            MMA_S8(acc[nt], a0, a1, a2, a3, b0, b1);
        }
    }

#pragma unroll
    for (int nt = 0; nt < 2; ++nt)
#pragma unroll
        for (int k = 0; k < 4; ++k) {
            int c = nt * 8 + (lane & 3) * 2 + (k & 1);
            int r = row0 + (lane >> 2) + (k >> 1) * 8;
            if (c < 10) {
                float sv = gamma[c] * rsqrtf(var[c] + EPS_BN);
                out[(size_t)r * 10 + c] =
                    sv * ((float)acc[nt][k] + bias[c] - mean[c]) + beta[c];
            }
        }
}

// ===================== launch =====================
extern "C" void kernel_launch(void* const* d_in, const int* in_sizes, int n_in,
                              void* d_out, int out_size) {
    const float* x  = (const float*)d_in[0];
    const float* W1 = (const float*)d_in[1];
    const float* b1 = (const float*)d_in[2];
    const float* g1 = (const float*)d_in[3];
    const float* be1= (const float*)d_in[4];
    const float* m1 = (const float*)d_in[5];
    const float* v1 = (const float*)d_in[6];
    const float* W2 = (const float*)d_in[7];
    const float* b2 = (const float*)d_in[8];
    const float* g2 = (const float*)d_in[9];
    const float* be2= (const float*)d_in[10];
    const float* m2 = (const float*)d_in[11];
    const float* v2 = (const float*)d_in[12];
    const float* W3 = (const float*)d_in[13];
    const float* b3 = (const float*)d_in[14];
    const float* g3 = (const float*)d_in[15];
    const float* be3= (const float*)d_in[16];
    const float* m3 = (const float*)d_in[17];
    const float* v3 = (const float*)d_in[18];
    const float* W4 = (const float*)d_in[19];
    const float* b4 = (const float*)d_in[20];
    const float* g4 = (const float*)d_in[21];
    const float* be4= (const float*)d_in[22];
    const float* m4 = (const float*)d_in[23];
    const float* v4 = (const float*)d_in[24];

    int8_t *a0, *a1, *a2, *w1, *w2, *w3, *w4;
    cudaGetSymbolAddress((void**)&a0, g_A0);
    cudaGetSymbolAddress((void**)&a1, g_A1);
    cudaGetSymbolAddress((void**)&a2, g_A2);
    cudaGetSymbolAddress((void**)&w1, g_W1);
    cudaGetSymbolAddress((void**)&w2, g_W2);
    cudaGetSymbolAddress((void**)&w3, g_W3);
    cudaGetSymbolAddress((void**)&w4, g_W4);

    const int M = 32768;

    pack_all<<<3968, 256>>>(x, a0, W1, w1, W2, w2, W3, w3, W4, w4);

    cudaFuncSetAttribute(bgemm_bulk, cudaFuncAttributeMaxDynamicSharedMemorySize, SM_TOTAL);

    dim3 grid(8, M / 128);   // x = N tiles (128), y = M tiles (128)

    bgemm_bulk<<<grid, 256, SM_TOTAL>>>(a0, w1, 14, b1, g1, be1, m1, v1, a1);
    bgemm_bulk<<<grid, 256, SM_TOTAL>>>(a1, w2, 16, b2, g2, be2, m2, v2, a2);
    bgemm_bulk<<<grid, 256, SM_TOTAL>>>(a2, w3, 16, b3, g3, be3, m3, v3, a1);

    final_mma<<<M / 128, 256>>>(a1, w4, b4, g4, be4, m4, v4, (float*)d_out);
}